// round 9
// baseline (speedup 1.0000x reference)
#include <cuda_runtime.h>
#include <cuda_fp16.h>
#include <cstdint>

#define BB 4
#define SS 4096
#define DD 1024
#define MTOT (BB*SS)

#define BM 128
#define BN 256
#define BK 32
#define TILE_A 8192                 // 128 rows x 64B
#define TILE_BB 16384               // 256 rows x 64B
#define SMEM_BYTES 73728            // max(3*24576, 2*32768)

// ---------------- device scratch ----------------
__device__ __half g_xh [(size_t)MTOT*DD];
__device__ __half g_xl [(size_t)MTOT*DD];
__device__ __half g_Wth[(size_t)3*DD*DD];   // W^T hi: [z][n][k]
__device__ __half g_Qxh[(size_t)MTOT*DD];
__device__ __half g_Qxl[(size_t)MTOT*DD];
__device__ __half g_Kxh[(size_t)MTOT*DD];
__device__ float  g_Vx [(size_t)MTOT*DD];
__device__ __half g_Vth[(size_t)MTOT*DD];   // Vx^T hi: [b][d][s]
__device__ float  g_S  [(size_t)BB*SS*SS];
__device__ __half g_Ph [(size_t)BB*SS*SS];

// ---------------- asm helpers ----------------
__device__ __forceinline__ uint32_t smem_u32(const void* p){
    uint32_t a;
    asm("{ .reg .u64 t; cvta.to.shared.u64 t, %1; cvt.u32.u64 %0, t; }" : "=r"(a) : "l"(p));
    return a;
}
#define CPA(dst, src) asm volatile("cp.async.cg.shared.global [%0], [%1], 16;" :: "r"(dst), "l"(src))
#define CPC()  asm volatile("cp.async.commit_group;")

template<int N> __device__ __forceinline__ void cp_wait();
template<> __device__ __forceinline__ void cp_wait<0>(){ asm volatile("cp.async.wait_group 0;"); }
template<> __device__ __forceinline__ void cp_wait<1>(){ asm volatile("cp.async.wait_group 1;"); }

#define LDSM4(r0,r1,r2,r3,addr) \
    asm volatile("ldmatrix.sync.aligned.m8n8.x4.shared.b16 {%0,%1,%2,%3}, [%4];" \
        : "=r"(r0), "=r"(r1), "=r"(r2), "=r"(r3) : "r"(addr))

#define MMA(d, a, b) asm volatile( \
    "mma.sync.aligned.m16n8k16.row.col.f32.f16.f16.f32 " \
    "{%0,%1,%2,%3}, {%4,%5,%6,%7}, {%8,%9}, {%0,%1,%2,%3};" \
    : "+f"((d)[0]), "+f"((d)[1]), "+f"((d)[2]), "+f"((d)[3]) \
    : "r"((a)[0]), "r"((a)[1]), "r"((a)[2]), "r"((a)[3]), "r"((b)[0]), "r"((b)[1]))

__device__ __forceinline__ void split2(float v, __half& h, __half& l){
    h = __float2half(v);
    l = __float2half(v - __half2float(h));
}

// swizzled byte offset within a tile: row r, 16B chunk c (0..3)
__device__ __forceinline__ uint32_t swz(uint32_t r, uint32_t c){
    return r*64u + ((c ^ (r & 3u)) * 16u);
}

// ---------------- stage load (cp.async, swizzled): A(128r)[hi,lo?], B(256r) ----
template<bool SA>
__device__ __forceinline__ void load_stage(uint32_t sm,
    const __half* Ah, const __half* Al, size_t lda, int r0a,
    const __half* Bh, size_t ldb, int r0b,
    int k0, int tid)
{
#pragma unroll
    for (int i = 0; i < 2; i++){
        int id = tid + i*256;
        uint32_t r = (uint32_t)(id >> 2), c = (uint32_t)(id & 3);
        uint32_t so = swz(r, c);
        size_t goa = (size_t)(r0a + (int)r)*lda + k0 + c*8;
        CPA(sm + so, Ah + goa);
        if (SA) CPA(sm + TILE_A + so, Al + goa);
    }
    const uint32_t bbase = sm + (SA ? 2 : 1)*TILE_A;
#pragma unroll
    for (int i = 0; i < 4; i++){
        int id = tid + i*256;
        uint32_t r = (uint32_t)(id >> 2), c = (uint32_t)(id & 3);
        uint32_t so = swz(r, c);
        size_t gob = (size_t)(r0b + (int)r)*ldb + k0 + c*8;
        CPA(bbase + so, Bh + gob);
    }
}

// ---------------- stage compute: warp tile 64x64 ----------------
template<bool SA>
__device__ __forceinline__ void compute_stage(uint32_t sm, int lane, int wm, int wn,
                                              float acc[4][8][4])
{
    const uint32_t aAh = sm;
    const uint32_t aAl = sm + TILE_A;
    const uint32_t aBh = sm + (SA ? 2 : 1)*TILE_A;
    const int ar = lane & 15;
    const int ac = lane >> 4;
    const int br = (lane & 7) | ((lane >> 4) << 3);
    const int bc = (lane >> 3) & 1;
#pragma unroll
    for (int ks = 0; ks < 2; ks++){
        uint32_t ah[4][4], al[4][4], bh[8][2];
#pragma unroll
        for (int mi = 0; mi < 4; mi++){
            uint32_t r = (uint32_t)(wm*64 + mi*16 + ar);
            uint32_t off = swz(r, (uint32_t)(ks*2 + ac));
            LDSM4(ah[mi][0], ah[mi][1], ah[mi][2], ah[mi][3], aAh + off);
            if (SA) LDSM4(al[mi][0], al[mi][1], al[mi][2], al[mi][3], aAl + off);
        }
#pragma unroll
        for (int np = 0; np < 4; np++){
            uint32_t r = (uint32_t)(wn*64 + np*16 + br);
            uint32_t off = swz(r, (uint32_t)(ks*2 + bc));
            LDSM4(bh[2*np][0], bh[2*np][1], bh[2*np+1][0], bh[2*np+1][1], aBh + off);
        }
#pragma unroll
        for (int mi = 0; mi < 4; mi++)
#pragma unroll
            for (int ni = 0; ni < 8; ni++){
                MMA(acc[mi][ni], ah[mi], bh[ni]);
                if (SA) MMA(acc[mi][ni], al[mi], bh[ni]);
            }
    }
}

// ---------------- GEMM mainloop ----------------
template<bool SA, int NST>
__device__ __forceinline__ void gemm_run(uint32_t sm, int tid,
    const __half* Ah, const __half* Al, size_t lda, int r0a,
    const __half* Bh, size_t ldb, int r0b,
    int ktiles, float acc[4][8][4])
{
    constexpr int STAGE = (SA ? 2 : 1)*TILE_A + TILE_BB;
    const int lane = tid & 31, wid = tid >> 5;
    const int wm = wid & 1, wn = wid >> 1;
    const int kend = ktiles * BK;

#pragma unroll
    for (int s = 0; s < NST - 1; s++){
        int k = min(s * BK, kend - BK);
        load_stage<SA>(sm + s*STAGE, Ah, Al, lda, r0a, Bh, ldb, r0b, k, tid);
        CPC();
    }

    int buf = 0;
    int nxt = NST - 1;
    for (int kt = 0; kt < ktiles; kt++){
        cp_wait<NST-2>();
        __syncthreads();
        {
            int k = min((kt + NST - 1) * BK, kend - BK);
            load_stage<SA>(sm + nxt*STAGE, Ah, Al, lda, r0a, Bh, ldb, r0b, k, tid);
            CPC();
        }
        compute_stage<SA>(sm + buf*STAGE, lane, wm, wn, acc);
        buf = (buf + 1 == NST) ? 0 : buf + 1;
        nxt = (nxt + 1 == NST) ? 0 : nxt + 1;
    }
}

// ---------------- kernel 1: split x -> fp16 hi/lo ----------------
__global__ void k_split_x(const float* __restrict__ x){
    size_t i = ((size_t)blockIdx.x * 256 + threadIdx.x) * 4;
    float4 v = *reinterpret_cast<const float4*>(x + i);
    __half h[4], l[4];
    split2(v.x, h[0], l[0]); split2(v.y, h[1], l[1]);
    split2(v.z, h[2], l[2]); split2(v.w, h[3], l[3]);
    __half2 h01{h[0],h[1]}, h23{h[2],h[3]}, l01{l[0],l[1]}, l23{l[2],l[3]};
    *reinterpret_cast<__half2*>(g_xh + i)     = h01;
    *reinterpret_cast<__half2*>(g_xh + i + 2) = h23;
    *reinterpret_cast<__half2*>(g_xl + i)     = l01;
    *reinterpret_cast<__half2*>(g_xl + i + 2) = l23;
}

// ---------------- kernel 2: transpose weights (hi only) ----------------
__global__ void k_split_w(const float* __restrict__ Wq,
                          const float* __restrict__ Wk,
                          const float* __restrict__ Wv){
    const int z = blockIdx.z;
    const float* W = (z == 0) ? Wq : (z == 1) ? Wk : Wv;
    __half* H = g_Wth + (size_t)z*DD*DD;
    __shared__ float t[32][33];
    int tx = threadIdx.x, ty = threadIdx.y;
    int kb = blockIdx.y * 32, nb = blockIdx.x * 32;
#pragma unroll
    for (int j = 0; j < 4; j++)
        t[ty + j*8][tx] = W[(size_t)(kb + ty + j*8)*DD + nb + tx];
    __syncthreads();
#pragma unroll
    for (int j = 0; j < 4; j++){
        int n = nb + ty + j*8, k = kb + tx;
        H[(size_t)n*DD + k] = __float2half(t[tx][ty + j*8]);
    }
}

// ---------------- kernel 3a: Q projection (2-pass split) ----------------
__global__ void __launch_bounds__(256, 1) k_proj_q(){
    extern __shared__ __align__(128) char smem[];
    uint32_t sm = smem_u32(smem);
    const int tid = threadIdx.x;
    const int m0 = blockIdx.y*BM, n0 = blockIdx.x*BN;
    float acc[4][8][4] = {};
    gemm_run<true,2>(sm, tid, g_xh, g_xl, DD, m0, g_Wth, DD, n0, DD/BK, acc);
    const int lane = tid & 31, wid = tid >> 5, wm = wid & 1, wn = wid >> 1;
    const int r = lane >> 2, c = (lane & 3) * 2;
#pragma unroll
    for (int mi = 0; mi < 4; mi++)
#pragma unroll
        for (int ni = 0; ni < 8; ni++){
            int row = m0 + wm*64 + mi*16 + r;
            int col = n0 + wn*64 + ni*8 + c;
#pragma unroll
            for (int hrow = 0; hrow < 2; hrow++){
                float v0 = acc[mi][ni][hrow*2 + 0];
                float v1 = acc[mi][ni][hrow*2 + 1];
                size_t o = (size_t)(row + hrow*8)*DD + col;
                __half h0,l0,h1,l1;
                split2(v0, h0, l0); split2(v1, h1, l1);
                __half2 hp{h0,h1}, lp{l0,l1};
                *reinterpret_cast<__half2*>(g_Qxh + o) = hp;
                *reinterpret_cast<__half2*>(g_Qxl + o) = lp;
            }
        }
}

// ---------------- kernel 3b: K/V projections (1-pass) ----------------
__global__ void __launch_bounds__(256, 1) k_proj_kv(){
    extern __shared__ __align__(128) char smem[];
    uint32_t sm = smem_u32(smem);
    const int tid = threadIdx.x;
    const int z = blockIdx.z;                 // 0 -> K, 1 -> V
    const int m0 = blockIdx.y*BM, n0 = blockIdx.x*BN;
    float acc[4][8][4] = {};
    gemm_run<false,3>(sm, tid, g_xh, nullptr, DD, m0,
                      g_Wth + (size_t)(z+1)*DD*DD, DD, n0, DD/BK, acc);
    const int lane = tid & 31, wid = tid >> 5, wm = wid & 1, wn = wid >> 1;
    const int r = lane >> 2, c = (lane & 3) * 2;
#pragma unroll
    for (int mi = 0; mi < 4; mi++)
#pragma unroll
        for (int ni = 0; ni < 8; ni++){
            int row = m0 + wm*64 + mi*16 + r;
            int col = n0 + wn*64 + ni*8 + c;
#pragma unroll
            for (int hrow = 0; hrow < 2; hrow++){
                float v0 = acc[mi][ni][hrow*2 + 0];
                float v1 = acc[mi][ni][hrow*2 + 1];
                size_t o = (size_t)(row + hrow*8)*DD + col;
                if (z == 0){
                    __half2 hp{__float2half(v0), __float2half(v1)};
                    *reinterpret_cast<__half2*>(g_Kxh + o) = hp;
                } else {
                    *reinterpret_cast<float2*>(g_Vx + o) = make_float2(v0, v1);
                }
            }
        }
}

// ---------------- kernel 4: transpose Vx (hi only) ----------------
__global__ void k_vtrans(){
    const int b = blockIdx.z;
    const float* Vx = g_Vx + (size_t)b*SS*DD;
    __half* H = g_Vth + (size_t)b*DD*SS;
    __shared__ float t[32][33];
    int tx = threadIdx.x, ty = threadIdx.y;
    int s0 = blockIdx.y * 32, d0 = blockIdx.x * 32;
#pragma unroll
    for (int j = 0; j < 4; j++)
        t[ty + j*8][tx] = Vx[(size_t)(s0 + ty + j*8)*DD + d0 + tx];
    __syncthreads();
#pragma unroll
    for (int j = 0; j < 4; j++){
        int d = d0 + ty + j*8, s = s0 + tx;
        H[(size_t)d*SS + s] = __float2half(t[tx][ty + j*8]);
    }
}

// ---------------- kernel 5: scores (causal tiles, 2-pass) ----------------
__global__ void __launch_bounds__(256, 1) k_scores(){
    const int kt = blockIdx.x, qt = blockIdx.y, b = blockIdx.z;
    if (kt*BN > qt*BM + BM - 1) return;   // tile fully above diagonal
    extern __shared__ __align__(128) char smem[];
    uint32_t sm = smem_u32(smem);
    const int tid = threadIdx.x;
    float acc[4][8][4] = {};
    gemm_run<true,2>(sm, tid,
                     g_Qxh + (size_t)b*SS*DD, g_Qxl + (size_t)b*SS*DD, DD, qt*BM,
                     g_Kxh + (size_t)b*SS*DD, DD, kt*BN, DD/BK, acc);
    const int lane = tid & 31, wid = tid >> 5, wm = wid & 1, wn = wid >> 1;
    const int r = lane >> 2, c = (lane & 3) * 2;
    float* Sp = g_S + (size_t)b*SS*SS;
#pragma unroll
    for (int mi = 0; mi < 4; mi++)
#pragma unroll
        for (int ni = 0; ni < 8; ni++){
            int row = qt*BM + wm*64 + mi*16 + r;
            int col = kt*BN + wn*64 + ni*8 + c;
#pragma unroll
            for (int hrow = 0; hrow < 2; hrow++){
                size_t o = (size_t)(row + hrow*8)*SS + col;
                *reinterpret_cast<float2*>(Sp + o) =
                    make_float2(acc[mi][ni][hrow*2+0]*0.03125f,
                                acc[mi][ni][hrow*2+1]*0.03125f);
            }
        }
}

// ---------------- kernel 6: softmax -> fp16 probs + pad ----------------
__global__ void k_softmax(){
    const int q = blockIdx.x;
    const int b = blockIdx.y;
    const float* row = g_S + (size_t)b*SS*SS + (size_t)q*SS;
    __half* Ph = g_Ph + (size_t)b*SS*SS + (size_t)q*SS;
    const int len = q + 1;

    __shared__ float buf[SS];
    __shared__ float red[256];
    const int tid = threadIdx.x;

    float mx = -1e30f;
    for (int i = tid; i < len; i += 256){
        float v = row[i];
        buf[i] = v;
        mx = fmaxf(mx, v);
    }
    red[tid] = mx;
    __syncthreads();
    for (int s = 128; s > 0; s >>= 1){
        if (tid < s) red[tid] = fmaxf(red[tid], red[tid + s]);
        __syncthreads();
    }
    mx = red[0];
    __syncthreads();

    float sum = 0.f;
    for (int i = tid; i < len; i += 256){
        float e = __expf(buf[i] - mx);
        buf[i] = e;
        sum += e;
    }
    red[tid] = sum;
    __syncthreads();
    for (int s = 128; s > 0; s >>= 1){
        if (tid < s) red[tid] += red[tid + s];
        __syncthreads();
    }
    const float inv = 1.0f / red[0];
    __syncthreads();

    for (int i = tid; i < len; i += 256)
        Ph[i] = __float2half(buf[i] * inv);
    // zero-pad to the 128-tile boundary so PV's diagonal tiles read zeros
    const int bound = ((q >> 7) + 1) << 7;
    const __half z = __float2half(0.f);
    for (int i = len + tid; i < bound; i += 256) Ph[i] = z;
}

// ---------------- kernel 7: O = P @ V (triangular K range, 1-pass) ----------------
__global__ void __launch_bounds__(256, 1) k_pv(float* __restrict__ Out){
    const int dt = blockIdx.x, qt = blockIdx.y, b = blockIdx.z;
    extern __shared__ __align__(128) char smem[];
    uint32_t sm = smem_u32(smem);
    const int tid = threadIdx.x;
    float acc[4][8][4] = {};
    const int ktiles = (qt + 1) * (BM / BK);   // keys up to (qt+1)*128
    gemm_run<false,3>(sm, tid,
                      g_Ph  + (size_t)b*SS*SS, nullptr, SS, qt*BM,
                      g_Vth + (size_t)b*DD*SS, SS, dt*BN, ktiles, acc);
    const int lane = tid & 31, wid = tid >> 5, wm = wid & 1, wn = wid >> 1;
    const int r = lane >> 2, c = (lane & 3) * 2;
#pragma unroll
    for (int mi = 0; mi < 4; mi++)
#pragma unroll
        for (int ni = 0; ni < 8; ni++){
            int row = qt*BM + wm*64 + mi*16 + r;
            int col = dt*BN + wn*64 + ni*8 + c;
#pragma unroll
            for (int hrow = 0; hrow < 2; hrow++){
                size_t o = ((size_t)b*SS + row + hrow*8)*DD + col;
                *reinterpret_cast<float2*>(Out + o) =
                    make_float2(acc[mi][ni][hrow*2+0], acc[mi][ni][hrow*2+1]);
            }
        }
}

// ---------------- host ----------------
extern "C" void kernel_launch(void* const* d_in, const int* in_sizes, int n_in,
                              void* d_out, int out_size) {
    const float* x  = (const float*)d_in[0];
    const float* Q  = (const float*)d_in[1];
    const float* K  = (const float*)d_in[2];
    const float* V  = (const float*)d_in[3];
    float* out = (float*)d_out;

    cudaFuncSetAttribute(k_proj_q,  cudaFuncAttributeMaxDynamicSharedMemorySize, SMEM_BYTES);
    cudaFuncSetAttribute(k_proj_kv, cudaFuncAttributeMaxDynamicSharedMemorySize, SMEM_BYTES);
    cudaFuncSetAttribute(k_scores,  cudaFuncAttributeMaxDynamicSharedMemorySize, SMEM_BYTES);
    cudaFuncSetAttribute(k_pv,      cudaFuncAttributeMaxDynamicSharedMemorySize, SMEM_BYTES);

    k_split_x<<<(unsigned)((size_t)MTOT*DD/1024), 256>>>(x);
    k_split_w<<<dim3(DD/32, DD/32, 3), dim3(32, 8)>>>(Q, K, V);
    k_proj_q <<<dim3(DD/BN, MTOT/BM),    256, SMEM_BYTES>>>();
    k_proj_kv<<<dim3(DD/BN, MTOT/BM, 2), 256, SMEM_BYTES>>>();
    k_vtrans<<<dim3(DD/32, SS/32, BB), dim3(32, 8)>>>();
    k_scores<<<dim3(SS/BN, SS/BM, BB), 256, SMEM_BYTES>>>();
    k_softmax<<<dim3(SS, BB), 256>>>();
    k_pv<<<dim3(DD/BN, SS/BM, BB), 256, SMEM_BYTES>>>(out);
}

// round 10
// speedup vs baseline: 1.2535x; 1.2535x over previous
#include <cuda_runtime.h>
#include <cuda_fp16.h>
#include <cstdint>

#define BB 4
#define SS 4096
#define DD 1024
#define MTOT (BB*SS)

#define BM 128
#define BN 128
#define BK 32
#define TILE_B 8192                 // 128 rows x 64 bytes, swizzled
#define STAGE_B (2*TILE_B)          // A, B per stage = 16 KB
#define NSTAGE 3
#define SMEM_BYTES (NSTAGE*STAGE_B) // 48 KB -> 2 CTAs/SM

// ---------------- device scratch ----------------
__device__ __half g_xh [(size_t)MTOT*DD];
__device__ __half g_Wth[(size_t)3*DD*DD];   // W^T hi: [z][n][k]
__device__ __half g_Qxh[(size_t)MTOT*DD];
__device__ __half g_Kxh[(size_t)MTOT*DD];
__device__ float  g_Vx [(size_t)MTOT*DD];
__device__ __half g_Vth[(size_t)MTOT*DD];   // Vx^T hi: [b][d][s]
__device__ float  g_S  [(size_t)BB*SS*SS];
__device__ __half g_Ph [(size_t)BB*SS*SS];

// ---------------- asm helpers ----------------
__device__ __forceinline__ uint32_t smem_u32(const void* p){
    uint32_t a;
    asm("{ .reg .u64 t; cvta.to.shared.u64 t, %1; cvt.u32.u64 %0, t; }" : "=r"(a) : "l"(p));
    return a;
}
#define CPA(dst, src) asm volatile("cp.async.cg.shared.global [%0], [%1], 16;" :: "r"(dst), "l"(src))
#define CPC()  asm volatile("cp.async.commit_group;")
#define CPW1() asm volatile("cp.async.wait_group 1;")

#define LDSM4(r0,r1,r2,r3,addr) \
    asm volatile("ldmatrix.sync.aligned.m8n8.x4.shared.b16 {%0,%1,%2,%3}, [%4];" \
        : "=r"(r0), "=r"(r1), "=r"(r2), "=r"(r3) : "r"(addr))

#define MMA(d, a, b) asm volatile( \
    "mma.sync.aligned.m16n8k16.row.col.f32.f16.f16.f32 " \
    "{%0,%1,%2,%3}, {%4,%5,%6,%7}, {%8,%9}, {%0,%1,%2,%3};" \
    : "+f"((d)[0]), "+f"((d)[1]), "+f"((d)[2]), "+f"((d)[3]) \
    : "r"((a)[0]), "r"((a)[1]), "r"((a)[2]), "r"((a)[3]), "r"((b)[0]), "r"((b)[1]))

// swizzled byte offset within a tile: row r (0..127), 16B chunk c (0..3)
__device__ __forceinline__ uint32_t swz(uint32_t r, uint32_t c){
    return r*64u + ((c ^ (r & 3u)) * 16u);
}

// ---------------- stage load (cp.async, swizzled): A, B ----------------
__device__ __forceinline__ void load_stage(uint32_t sm,
    const __half* A, size_t lda, int r0a,
    const __half* B, size_t ldb, int r0b,
    int k0, int tid)
{
#pragma unroll
    for (int i = 0; i < 2; i++){
        int id = tid + i*256;                 // 0..511
        uint32_t r = (uint32_t)(id >> 2), c = (uint32_t)(id & 3);
        uint32_t so = swz(r, c);
        size_t goa = (size_t)(r0a + (int)r)*lda + k0 + c*8;
        size_t gob = (size_t)(r0b + (int)r)*ldb + k0 + c*8;
        CPA(sm + so,          A + goa);
        CPA(sm + TILE_B + so, B + gob);
    }
}

// ---------------- stage compute: warp tile 32x64, 1-pass ----------------
__device__ __forceinline__ void compute_stage(uint32_t sm, int lane, int wm, int wn,
                                              float acc[2][8][4])
{
    const uint32_t aA = sm;
    const uint32_t aB = sm + TILE_B;
    const int ar = lane & 15;
    const int ac = lane >> 4;
    const int br = (lane & 7) | ((lane >> 4) << 3);
    const int bc = (lane >> 3) & 1;
#pragma unroll
    for (int ks = 0; ks < 2; ks++){
        uint32_t a[2][4], bh[8][2];
#pragma unroll
        for (int mi = 0; mi < 2; mi++){
            uint32_t r = (uint32_t)(wm*32 + mi*16 + ar);
            uint32_t off = swz(r, (uint32_t)(ks*2 + ac));
            LDSM4(a[mi][0], a[mi][1], a[mi][2], a[mi][3], aA + off);
        }
#pragma unroll
        for (int np = 0; np < 4; np++){
            uint32_t r = (uint32_t)(wn*64 + np*16 + br);
            uint32_t off = swz(r, (uint32_t)(ks*2 + bc));
            LDSM4(bh[2*np][0], bh[2*np][1], bh[2*np+1][0], bh[2*np+1][1], aB + off);
        }
#pragma unroll
        for (int mi = 0; mi < 2; mi++)
#pragma unroll
            for (int ni = 0; ni < 8; ni++)
                MMA(acc[mi][ni], a[mi], bh[ni]);
    }
}

// ---------------- GEMM mainloop (3-stage pipeline, 1 sync/iter) ----------------
__device__ __forceinline__ void gemm_run(uint32_t sm, int tid,
    const __half* A, size_t lda, int r0a,
    const __half* B, size_t ldb, int r0b,
    int ktiles, float acc[2][8][4])
{
    const int lane = tid & 31, wid = tid >> 5;
    const int wm = wid & 3, wn = wid >> 2;
    const int kend = ktiles * BK;

#pragma unroll
    for (int s = 0; s < NSTAGE - 1; s++){
        int k = min(s * BK, kend - BK);
        load_stage(sm + s*STAGE_B, A, lda, r0a, B, ldb, r0b, k, tid);
        CPC();
    }

    int buf = 0;
    int nxt = NSTAGE - 1;
    for (int kt = 0; kt < ktiles; kt++){
        CPW1();
        __syncthreads();
        {
            int k = min((kt + NSTAGE - 1) * BK, kend - BK);
            load_stage(sm + nxt*STAGE_B, A, lda, r0a, B, ldb, r0b, k, tid);
            CPC();
        }
        compute_stage(sm + buf*STAGE_B, lane, wm, wn, acc);
        buf = (buf + 1 == NSTAGE) ? 0 : buf + 1;
        nxt = (nxt + 1 == NSTAGE) ? 0 : nxt + 1;
    }
}

// ---------------- kernel 1: x -> fp16 ----------------
__global__ void k_half_x(const float* __restrict__ x){
    size_t i = ((size_t)blockIdx.x * 256 + threadIdx.x) * 4;
    float4 v = *reinterpret_cast<const float4*>(x + i);
    __half2 h01{__float2half(v.x), __float2half(v.y)};
    __half2 h23{__float2half(v.z), __float2half(v.w)};
    *reinterpret_cast<__half2*>(g_xh + i)     = h01;
    *reinterpret_cast<__half2*>(g_xh + i + 2) = h23;
}

// ---------------- kernel 2: transpose weights -> fp16 ----------------
__global__ void k_split_w(const float* __restrict__ Wq,
                          const float* __restrict__ Wk,
                          const float* __restrict__ Wv){
    const int z = blockIdx.z;
    const float* W = (z == 0) ? Wq : (z == 1) ? Wk : Wv;
    __half* H = g_Wth + (size_t)z*DD*DD;
    __shared__ float t[32][33];
    int tx = threadIdx.x, ty = threadIdx.y;
    int kb = blockIdx.y * 32, nb = blockIdx.x * 32;
#pragma unroll
    for (int j = 0; j < 4; j++)
        t[ty + j*8][tx] = W[(size_t)(kb + ty + j*8)*DD + nb + tx];
    __syncthreads();
#pragma unroll
    for (int j = 0; j < 4; j++){
        int n = nb + ty + j*8, k = kb + tx;
        H[(size_t)n*DD + k] = __float2half(t[tx][ty + j*8]);
    }
}

// ---------------- kernel 3: projections (1-pass, all three) ----------------
__global__ void __launch_bounds__(256, 2) k_proj(){
    extern __shared__ __align__(128) char smem[];
    uint32_t sm = smem_u32(smem);
    const int tid = threadIdx.x;
    const int z = blockIdx.z;                 // 0->Q, 1->K, 2->V
    const int m0 = blockIdx.y*BM, n0 = blockIdx.x*BN;
    float acc[2][8][4] = {};
    gemm_run(sm, tid, g_xh, DD, m0,
             g_Wth + (size_t)z*DD*DD, DD, n0, DD/BK, acc);
    const int lane = tid & 31, wid = tid >> 5, wm = wid & 3, wn = wid >> 2;
    const int r = lane >> 2, c = (lane & 3) * 2;
#pragma unroll
    for (int mi = 0; mi < 2; mi++)
#pragma unroll
        for (int ni = 0; ni < 8; ni++){
            int row = m0 + wm*32 + mi*16 + r;
            int col = n0 + wn*64 + ni*8 + c;
#pragma unroll
            for (int hrow = 0; hrow < 2; hrow++){
                float v0 = acc[mi][ni][hrow*2 + 0];
                float v1 = acc[mi][ni][hrow*2 + 1];
                size_t o = (size_t)(row + hrow*8)*DD + col;
                if (z == 2){
                    *reinterpret_cast<float2*>(g_Vx + o) = make_float2(v0, v1);
                } else {
                    __half* H = z ? g_Kxh : g_Qxh;
                    __half2 hp{__float2half(v0), __float2half(v1)};
                    *reinterpret_cast<__half2*>(H + o) = hp;
                }
            }
        }
}

// ---------------- kernel 4: transpose Vx -> fp16 ----------------
__global__ void k_vtrans(){
    const int b = blockIdx.z;
    const float* Vx = g_Vx + (size_t)b*SS*DD;
    __half* H = g_Vth + (size_t)b*DD*SS;
    __shared__ float t[32][33];
    int tx = threadIdx.x, ty = threadIdx.y;
    int s0 = blockIdx.y * 32, d0 = blockIdx.x * 32;
#pragma unroll
    for (int j = 0; j < 4; j++)
        t[ty + j*8][tx] = Vx[(size_t)(s0 + ty + j*8)*DD + d0 + tx];
    __syncthreads();
#pragma unroll
    for (int j = 0; j < 4; j++){
        int d = d0 + ty + j*8, s = s0 + tx;
        H[(size_t)d*SS + s] = __float2half(t[tx][ty + j*8]);
    }
}

// ---------------- kernel 5: scores (lower-tri tiles, 1-pass) ----------------
__global__ void __launch_bounds__(256, 2) k_scores(){
    const int kt = blockIdx.x, qt = blockIdx.y, b = blockIdx.z;
    if (kt > qt) return;
    extern __shared__ __align__(128) char smem[];
    uint32_t sm = smem_u32(smem);
    const int tid = threadIdx.x;
    float acc[2][8][4] = {};
    gemm_run(sm, tid,
             g_Qxh + (size_t)b*SS*DD, DD, qt*BM,
             g_Kxh + (size_t)b*SS*DD, DD, kt*BN, DD/BK, acc);
    const int lane = tid & 31, wid = tid >> 5, wm = wid & 3, wn = wid >> 2;
    const int r = lane >> 2, c = (lane & 3) * 2;
    float* Sp = g_S + (size_t)b*SS*SS;
#pragma unroll
    for (int mi = 0; mi < 2; mi++)
#pragma unroll
        for (int ni = 0; ni < 8; ni++){
            int row = qt*BM + wm*32 + mi*16 + r;
            int col = kt*BN + wn*64 + ni*8 + c;
#pragma unroll
            for (int hrow = 0; hrow < 2; hrow++){
                size_t o = (size_t)(row + hrow*8)*SS + col;
                *reinterpret_cast<float2*>(Sp + o) =
                    make_float2(acc[mi][ni][hrow*2+0]*0.03125f,
                                acc[mi][ni][hrow*2+1]*0.03125f);
            }
        }
}

// ---------------- kernel 6: softmax -> fp16 probs + pad ----------------
__global__ void k_softmax(){
    const int q = blockIdx.x;
    const int b = blockIdx.y;
    const float* row = g_S + (size_t)b*SS*SS + (size_t)q*SS;
    __half* Ph = g_Ph + (size_t)b*SS*SS + (size_t)q*SS;
    const int len = q + 1;

    __shared__ float buf[SS];
    __shared__ float red[256];
    const int tid = threadIdx.x;

    float mx = -1e30f;
    for (int i = tid; i < len; i += 256){
        float v = row[i];
        buf[i] = v;
        mx = fmaxf(mx, v);
    }
    red[tid] = mx;
    __syncthreads();
    for (int s = 128; s > 0; s >>= 1){
        if (tid < s) red[tid] = fmaxf(red[tid], red[tid + s]);
        __syncthreads();
    }
    mx = red[0];
    __syncthreads();

    float sum = 0.f;
    for (int i = tid; i < len; i += 256){
        float e = __expf(buf[i] - mx);
        buf[i] = e;
        sum += e;
    }
    red[tid] = sum;
    __syncthreads();
    for (int s = 128; s > 0; s >>= 1){
        if (tid < s) red[tid] += red[tid + s];
        __syncthreads();
    }
    const float inv = 1.0f / red[0];
    __syncthreads();

    for (int i = tid; i < len; i += 256)
        Ph[i] = __float2half(buf[i] * inv);
    // zero-pad to the 128-tile boundary so PV's diagonal tiles read zeros
    const int bound = ((q >> 7) + 1) << 7;
    const __half z = __float2half(0.f);
    for (int i = len + tid; i < bound; i += 256) Ph[i] = z;
}

// ---------------- kernel 7: O = P @ V (triangular K range, 1-pass) ----------------
__global__ void __launch_bounds__(256, 2) k_pv(float* __restrict__ Out){
    const int dt = blockIdx.x, qt = blockIdx.y, b = blockIdx.z;
    extern __shared__ __align__(128) char smem[];
    uint32_t sm = smem_u32(smem);
    const int tid = threadIdx.x;
    float acc[2][8][4] = {};
    const int ktiles = (qt + 1) * (BM / BK);   // keys up to (qt+1)*128
    gemm_run(sm, tid,
             g_Ph  + (size_t)b*SS*SS, SS, qt*BM,
             g_Vth + (size_t)b*DD*SS, SS, dt*BN, ktiles, acc);
    const int lane = tid & 31, wid = tid >> 5, wm = wid & 3, wn = wid >> 2;
    const int r = lane >> 2, c = (lane & 3) * 2;
#pragma unroll
    for (int mi = 0; mi < 2; mi++)
#pragma unroll
        for (int ni = 0; ni < 8; ni++){
            int row = qt*BM + wm*32 + mi*16 + r;
            int col = dt*BN + wn*64 + ni*8 + c;
#pragma unroll
            for (int hrow = 0; hrow < 2; hrow++){
                size_t o = ((size_t)b*SS + row + hrow*8)*DD + col;
                *reinterpret_cast<float2*>(Out + o) =
                    make_float2(acc[mi][ni][hrow*2+0], acc[mi][ni][hrow*2+1]);
            }
        }
}

// ---------------- host ----------------
extern "C" void kernel_launch(void* const* d_in, const int* in_sizes, int n_in,
                              void* d_out, int out_size) {
    const float* x  = (const float*)d_in[0];
    const float* Q  = (const float*)d_in[1];
    const float* K  = (const float*)d_in[2];
    const float* V  = (const float*)d_in[3];
    float* out = (float*)d_out;

    cudaFuncSetAttribute(k_proj,   cudaFuncAttributeMaxDynamicSharedMemorySize, SMEM_BYTES);
    cudaFuncSetAttribute(k_scores, cudaFuncAttributeMaxDynamicSharedMemorySize, SMEM_BYTES);
    cudaFuncSetAttribute(k_pv,     cudaFuncAttributeMaxDynamicSharedMemorySize, SMEM_BYTES);

    k_half_x<<<(unsigned)((size_t)MTOT*DD/1024), 256>>>(x);
    k_split_w<<<dim3(DD/32, DD/32, 3), dim3(32, 8)>>>(Q, K, V);
    k_proj<<<dim3(DD/BN, MTOT/BM, 3), 256, SMEM_BYTES>>>();
    k_vtrans<<<dim3(DD/32, SS/32, BB), dim3(32, 8)>>>();
    k_scores<<<dim3(SS/BN, SS/BM, BB), 256, SMEM_BYTES>>>();
    k_softmax<<<dim3(SS, BB), 256>>>();
    k_pv<<<dim3(DD/BN, SS/BM, BB), 256, SMEM_BYTES>>>(out);
}

// round 11
// speedup vs baseline: 1.3693x; 1.0924x over previous
#include <cuda_runtime.h>
#include <cuda_fp16.h>
#include <cstdint>

#define BB 4
#define SS 4096
#define DD 1024
#define MTOT (BB*SS)

#define BM 128
#define BN 128
#define BK 32
#define TILE_B 8192                 // 128 rows x 64 bytes, swizzled
#define STAGE_B (2*TILE_B)          // A, B per stage = 16 KB
#define NSTAGE 3
#define SMEM_BYTES (NSTAGE*STAGE_B) // 48 KB -> 2 CTAs/SM

// ---------------- device scratch ----------------
__device__ __half g_xh [(size_t)MTOT*DD];
__device__ __half g_Qh [(size_t)DD*DD];     // Q weight, fp16 row-major
__device__ __half g_Kh [(size_t)DD*DD];     // K weight, fp16 row-major
__device__ __half g_Wtv[(size_t)DD*DD];     // V^T: [n][k]
__device__ __half g_Mt [(size_t)DD*DD];     // (K Q^T): B-operand for y = x@M
__device__ __half g_Yh [(size_t)MTOT*DD];   // y = x @ (Q K^T)
__device__ float  g_Vx [(size_t)MTOT*DD];
__device__ __half g_Vth[(size_t)MTOT*DD];   // Vx^T: [b][d][s]
__device__ float  g_S  [(size_t)BB*SS*SS];
__device__ __half g_Ph [(size_t)BB*SS*SS];

// ---------------- asm helpers ----------------
__device__ __forceinline__ uint32_t smem_u32(const void* p){
    uint32_t a;
    asm("{ .reg .u64 t; cvta.to.shared.u64 t, %1; cvt.u32.u64 %0, t; }" : "=r"(a) : "l"(p));
    return a;
}
#define CPA(dst, src) asm volatile("cp.async.cg.shared.global [%0], [%1], 16;" :: "r"(dst), "l"(src))
#define CPC()  asm volatile("cp.async.commit_group;")
#define CPW1() asm volatile("cp.async.wait_group 1;")

#define LDSM4(r0,r1,r2,r3,addr) \
    asm volatile("ldmatrix.sync.aligned.m8n8.x4.shared.b16 {%0,%1,%2,%3}, [%4];" \
        : "=r"(r0), "=r"(r1), "=r"(r2), "=r"(r3) : "r"(addr))

#define MMA(d, a, b) asm volatile( \
    "mma.sync.aligned.m16n8k16.row.col.f32.f16.f16.f32 " \
    "{%0,%1,%2,%3}, {%4,%5,%6,%7}, {%8,%9}, {%0,%1,%2,%3};" \
    : "+f"((d)[0]), "+f"((d)[1]), "+f"((d)[2]), "+f"((d)[3]) \
    : "r"((a)[0]), "r"((a)[1]), "r"((a)[2]), "r"((a)[3]), "r"((b)[0]), "r"((b)[1]))

// swizzled byte offset within a tile: row r (0..127), 16B chunk c (0..3)
__device__ __forceinline__ uint32_t swz(uint32_t r, uint32_t c){
    return r*64u + ((c ^ (r & 3u)) * 16u);
}

// ---------------- stage load (cp.async, swizzled): A, B ----------------
__device__ __forceinline__ void load_stage(uint32_t sm,
    const __half* A, size_t lda, int r0a,
    const __half* B, size_t ldb, int r0b,
    int k0, int tid)
{
#pragma unroll
    for (int i = 0; i < 2; i++){
        int id = tid + i*256;                 // 0..511
        uint32_t r = (uint32_t)(id >> 2), c = (uint32_t)(id & 3);
        uint32_t so = swz(r, c);
        size_t goa = (size_t)(r0a + (int)r)*lda + k0 + c*8;
        size_t gob = (size_t)(r0b + (int)r)*ldb + k0 + c*8;
        CPA(sm + so,          A + goa);
        CPA(sm + TILE_B + so, B + gob);
    }
}

// ---------------- stage compute: warp tile 32x64, 1-pass ----------------
__device__ __forceinline__ void compute_stage(uint32_t sm, int lane, int wm, int wn,
                                              float acc[2][8][4])
{
    const uint32_t aA = sm;
    const uint32_t aB = sm + TILE_B;
    const int ar = lane & 15;
    const int ac = lane >> 4;
    const int br = (lane & 7) | ((lane >> 4) << 3);
    const int bc = (lane >> 3) & 1;
#pragma unroll
    for (int ks = 0; ks < 2; ks++){
        uint32_t a[2][4], bh[8][2];
#pragma unroll
        for (int mi = 0; mi < 2; mi++){
            uint32_t r = (uint32_t)(wm*32 + mi*16 + ar);
            uint32_t off = swz(r, (uint32_t)(ks*2 + ac));
            LDSM4(a[mi][0], a[mi][1], a[mi][2], a[mi][3], aA + off);
        }
#pragma unroll
        for (int np = 0; np < 4; np++){
            uint32_t r = (uint32_t)(wn*64 + np*16 + br);
            uint32_t off = swz(r, (uint32_t)(ks*2 + bc));
            LDSM4(bh[2*np][0], bh[2*np][1], bh[2*np+1][0], bh[2*np+1][1], aB + off);
        }
#pragma unroll
        for (int mi = 0; mi < 2; mi++)
#pragma unroll
            for (int ni = 0; ni < 8; ni++)
                MMA(acc[mi][ni], a[mi], bh[ni]);
    }
}

// ---------------- GEMM mainloop (3-stage pipeline, 1 sync/iter) ----------------
__device__ __forceinline__ void gemm_run(uint32_t sm, int tid,
    const __half* A, size_t lda, int r0a,
    const __half* B, size_t ldb, int r0b,
    int ktiles, float acc[2][8][4])
{
    const int lane = tid & 31, wid = tid >> 5;
    const int wm = wid & 3, wn = wid >> 2;
    const int kend = ktiles * BK;

#pragma unroll
    for (int s = 0; s < NSTAGE - 1; s++){
        int k = min(s * BK, kend - BK);
        load_stage(sm + s*STAGE_B, A, lda, r0a, B, ldb, r0b, k, tid);
        CPC();
    }

    int buf = 0;
    int nxt = NSTAGE - 1;
    for (int kt = 0; kt < ktiles; kt++){
        CPW1();
        __syncthreads();
        {
            int k = min((kt + NSTAGE - 1) * BK, kend - BK);
            load_stage(sm + nxt*STAGE_B, A, lda, r0a, B, ldb, r0b, k, tid);
            CPC();
        }
        compute_stage(sm + buf*STAGE_B, lane, wm, wn, acc);
        buf = (buf + 1 == NSTAGE) ? 0 : buf + 1;
        nxt = (nxt + 1 == NSTAGE) ? 0 : nxt + 1;
    }
}

// ---------------- kernel 1: x -> fp16 ----------------
__global__ void k_half_x(const float* __restrict__ x){
    size_t i = ((size_t)blockIdx.x * 256 + threadIdx.x) * 4;
    float4 v = *reinterpret_cast<const float4*>(x + i);
    __half2 h01{__float2half(v.x), __float2half(v.y)};
    __half2 h23{__float2half(v.z), __float2half(v.w)};
    *reinterpret_cast<__half2*>(g_xh + i)     = h01;
    *reinterpret_cast<__half2*>(g_xh + i + 2) = h23;
}

// ---------------- kernel 2a: Q,K weights -> fp16 row-major ----------------
__global__ void k_half_w(const float* __restrict__ Wq,
                         const float* __restrict__ Wk){
    const float* W = blockIdx.y ? Wk : Wq;
    __half* H      = blockIdx.y ? g_Kh : g_Qh;
    size_t i = ((size_t)blockIdx.x * 256 + threadIdx.x) * 4;
    float4 v = *reinterpret_cast<const float4*>(W + i);
    __half2 h01{__float2half(v.x), __float2half(v.y)};
    __half2 h23{__float2half(v.z), __float2half(v.w)};
    *reinterpret_cast<__half2*>(H + i)     = h01;
    *reinterpret_cast<__half2*>(H + i + 2) = h23;
}

// ---------------- kernel 2b: transpose V -> fp16 ----------------
__global__ void k_wtrans(const float* __restrict__ Wv){
    __shared__ float t[32][33];
    int tx = threadIdx.x, ty = threadIdx.y;
    int kb = blockIdx.y * 32, nb = blockIdx.x * 32;
#pragma unroll
    for (int j = 0; j < 4; j++)
        t[ty + j*8][tx] = Wv[(size_t)(kb + ty + j*8)*DD + nb + tx];
    __syncthreads();
#pragma unroll
    for (int j = 0; j < 4; j++){
        int n = nb + ty + j*8, k = kb + tx;
        g_Wtv[(size_t)n*DD + k] = __float2half(t[tx][ty + j*8]);
    }
}

// ---------------- kernel 3: Mt = K @ Q^T (B-operand of y = x@M) ----------------
__global__ void __launch_bounds__(256, 2) k_M(){
    extern __shared__ __align__(128) char smem[];
    uint32_t sm = smem_u32(smem);
    const int tid = threadIdx.x;
    const int m0 = blockIdx.y*BM, n0 = blockIdx.x*BN;
    float acc[2][8][4] = {};
    gemm_run(sm, tid, g_Kh, DD, m0, g_Qh, DD, n0, DD/BK, acc);
    const int lane = tid & 31, wid = tid >> 5, wm = wid & 3, wn = wid >> 2;
    const int r = lane >> 2, c = (lane & 3) * 2;
#pragma unroll
    for (int mi = 0; mi < 2; mi++)
#pragma unroll
        for (int ni = 0; ni < 8; ni++){
            int row = m0 + wm*32 + mi*16 + r;
            int col = n0 + wn*64 + ni*8 + c;
#pragma unroll
            for (int hrow = 0; hrow < 2; hrow++){
                __half2 hp{__float2half(acc[mi][ni][hrow*2+0]),
                           __float2half(acc[mi][ni][hrow*2+1])};
                *reinterpret_cast<__half2*>(g_Mt + (size_t)(row + hrow*8)*DD + col) = hp;
            }
        }
}

// ---------------- kernel 4: V projection (1-pass) ----------------
__global__ void __launch_bounds__(256, 2) k_proj_v(){
    extern __shared__ __align__(128) char smem[];
    uint32_t sm = smem_u32(smem);
    const int tid = threadIdx.x;
    const int m0 = blockIdx.y*BM, n0 = blockIdx.x*BN;
    float acc[2][8][4] = {};
    gemm_run(sm, tid, g_xh, DD, m0, g_Wtv, DD, n0, DD/BK, acc);
    const int lane = tid & 31, wid = tid >> 5, wm = wid & 3, wn = wid >> 2;
    const int r = lane >> 2, c = (lane & 3) * 2;
#pragma unroll
    for (int mi = 0; mi < 2; mi++)
#pragma unroll
        for (int ni = 0; ni < 8; ni++){
            int row = m0 + wm*32 + mi*16 + r;
            int col = n0 + wn*64 + ni*8 + c;
#pragma unroll
            for (int hrow = 0; hrow < 2; hrow++){
                size_t o = (size_t)(row + hrow*8)*DD + col;
                *reinterpret_cast<float2*>(g_Vx + o) =
                    make_float2(acc[mi][ni][hrow*2+0], acc[mi][ni][hrow*2+1]);
            }
        }
}

// ---------------- kernel 5: y = x @ M (B = Mt) ----------------
__global__ void __launch_bounds__(256, 2) k_y(){
    extern __shared__ __align__(128) char smem[];
    uint32_t sm = smem_u32(smem);
    const int tid = threadIdx.x;
    const int m0 = blockIdx.y*BM, n0 = blockIdx.x*BN;
    float acc[2][8][4] = {};
    gemm_run(sm, tid, g_xh, DD, m0, g_Mt, DD, n0, DD/BK, acc);
    const int lane = tid & 31, wid = tid >> 5, wm = wid & 3, wn = wid >> 2;
    const int r = lane >> 2, c = (lane & 3) * 2;
#pragma unroll
    for (int mi = 0; mi < 2; mi++)
#pragma unroll
        for (int ni = 0; ni < 8; ni++){
            int row = m0 + wm*32 + mi*16 + r;
            int col = n0 + wn*64 + ni*8 + c;
#pragma unroll
            for (int hrow = 0; hrow < 2; hrow++){
                __half2 hp{__float2half(acc[mi][ni][hrow*2+0]),
                           __float2half(acc[mi][ni][hrow*2+1])};
                *reinterpret_cast<__half2*>(g_Yh + (size_t)(row + hrow*8)*DD + col) = hp;
            }
        }
}

// ---------------- kernel 6: transpose Vx -> fp16 ----------------
__global__ void k_vtrans(){
    const int b = blockIdx.z;
    const float* Vx = g_Vx + (size_t)b*SS*DD;
    __half* H = g_Vth + (size_t)b*DD*SS;
    __shared__ float t[32][33];
    int tx = threadIdx.x, ty = threadIdx.y;
    int s0 = blockIdx.y * 32, d0 = blockIdx.x * 32;
#pragma unroll
    for (int j = 0; j < 4; j++)
        t[ty + j*8][tx] = Vx[(size_t)(s0 + ty + j*8)*DD + d0 + tx];
    __syncthreads();
#pragma unroll
    for (int j = 0; j < 4; j++){
        int d = d0 + ty + j*8, s = s0 + tx;
        H[(size_t)d*SS + s] = __float2half(t[tx][ty + j*8]);
    }
}

// ---------------- kernel 7: scores = y @ x^T (lower-tri tiles) ----------------
__global__ void __launch_bounds__(256, 2) k_scores(){
    const int kt = blockIdx.x, qt = blockIdx.y, b = blockIdx.z;
    if (kt > qt) return;
    extern __shared__ __align__(128) char smem[];
    uint32_t sm = smem_u32(smem);
    const int tid = threadIdx.x;
    float acc[2][8][4] = {};
    gemm_run(sm, tid,
             g_Yh + (size_t)b*SS*DD, DD, qt*BM,
             g_xh + (size_t)b*SS*DD, DD, kt*BN, DD/BK, acc);
    const int lane = tid & 31, wid = tid >> 5, wm = wid & 3, wn = wid >> 2;
    const int r = lane >> 2, c = (lane & 3) * 2;
    float* Sp = g_S + (size_t)b*SS*SS;
#pragma unroll
    for (int mi = 0; mi < 2; mi++)
#pragma unroll
        for (int ni = 0; ni < 8; ni++){
            int row = qt*BM + wm*32 + mi*16 + r;
            int col = kt*BN + wn*64 + ni*8 + c;
#pragma unroll
            for (int hrow = 0; hrow < 2; hrow++){
                size_t o = (size_t)(row + hrow*8)*SS + col;
                *reinterpret_cast<float2*>(Sp + o) =
                    make_float2(acc[mi][ni][hrow*2+0]*0.03125f,
                                acc[mi][ni][hrow*2+1]*0.03125f);
            }
        }
}

// ---------------- kernel 8: softmax -> fp16 probs + pad ----------------
__global__ void k_softmax(){
    const int q = blockIdx.x;
    const int b = blockIdx.y;
    const float* row = g_S + (size_t)b*SS*SS + (size_t)q*SS;
    __half* Ph = g_Ph + (size_t)b*SS*SS + (size_t)q*SS;
    const int len = q + 1;

    __shared__ float buf[SS];
    __shared__ float red[256];
    const int tid = threadIdx.x;

    float mx = -1e30f;
    for (int i = tid; i < len; i += 256){
        float v = row[i];
        buf[i] = v;
        mx = fmaxf(mx, v);
    }
    red[tid] = mx;
    __syncthreads();
    for (int s = 128; s > 0; s >>= 1){
        if (tid < s) red[tid] = fmaxf(red[tid], red[tid + s]);
        __syncthreads();
    }
    mx = red[0];
    __syncthreads();

    float sum = 0.f;
    for (int i = tid; i < len; i += 256){
        float e = __expf(buf[i] - mx);
        buf[i] = e;
        sum += e;
    }
    red[tid] = sum;
    __syncthreads();
    for (int s = 128; s > 0; s >>= 1){
        if (tid < s) red[tid] += red[tid + s];
        __syncthreads();
    }
    const float inv = 1.0f / red[0];
    __syncthreads();

    for (int i = tid; i < len; i += 256)
        Ph[i] = __float2half(buf[i] * inv);
    // zero-pad to the 128-tile boundary so PV's diagonal tiles read zeros
    const int bound = ((q >> 7) + 1) << 7;
    const __half z = __float2half(0.f);
    for (int i = len + tid; i < bound; i += 256) Ph[i] = z;
}

// ---------------- kernel 9: O = P @ V (triangular K range) ----------------
__global__ void __launch_bounds__(256, 2) k_pv(float* __restrict__ Out){
    const int dt = blockIdx.x, qt = blockIdx.y, b = blockIdx.z;
    extern __shared__ __align__(128) char smem[];
    uint32_t sm = smem_u32(smem);
    const int tid = threadIdx.x;
    float acc[2][8][4] = {};
    const int ktiles = (qt + 1) * (BM / BK);   // keys up to (qt+1)*128
    gemm_run(sm, tid,
             g_Ph  + (size_t)b*SS*SS, SS, qt*BM,
             g_Vth + (size_t)b*DD*SS, SS, dt*BN, ktiles, acc);
    const int lane = tid & 31, wid = tid >> 5, wm = wid & 3, wn = wid >> 2;
    const int r = lane >> 2, c = (lane & 3) * 2;
#pragma unroll
    for (int mi = 0; mi < 2; mi++)
#pragma unroll
        for (int ni = 0; ni < 8; ni++){
            int row = qt*BM + wm*32 + mi*16 + r;
            int col = dt*BN + wn*64 + ni*8 + c;
#pragma unroll
            for (int hrow = 0; hrow < 2; hrow++){
                size_t o = ((size_t)b*SS + row + hrow*8)*DD + col;
                *reinterpret_cast<float2*>(Out + o) =
                    make_float2(acc[mi][ni][hrow*2+0], acc[mi][ni][hrow*2+1]);
            }
        }
}

// ---------------- host ----------------
extern "C" void kernel_launch(void* const* d_in, const int* in_sizes, int n_in,
                              void* d_out, int out_size) {
    const float* x  = (const float*)d_in[0];
    const float* Q  = (const float*)d_in[1];
    const float* K  = (const float*)d_in[2];
    const float* V  = (const float*)d_in[3];
    float* out = (float*)d_out;

    cudaFuncSetAttribute(k_M,      cudaFuncAttributeMaxDynamicSharedMemorySize, SMEM_BYTES);
    cudaFuncSetAttribute(k_proj_v, cudaFuncAttributeMaxDynamicSharedMemorySize, SMEM_BYTES);
    cudaFuncSetAttribute(k_y,      cudaFuncAttributeMaxDynamicSharedMemorySize, SMEM_BYTES);
    cudaFuncSetAttribute(k_scores, cudaFuncAttributeMaxDynamicSharedMemorySize, SMEM_BYTES);
    cudaFuncSetAttribute(k_pv,     cudaFuncAttributeMaxDynamicSharedMemorySize, SMEM_BYTES);

    k_half_x<<<(unsigned)((size_t)MTOT*DD/1024), 256>>>(x);
    k_half_w<<<dim3(DD*DD/1024, 2), 256>>>(Q, K);
    k_wtrans<<<dim3(DD/32, DD/32), dim3(32, 8)>>>(V);
    k_M<<<dim3(DD/BN, DD/BM), 256, SMEM_BYTES>>>();
    k_proj_v<<<dim3(DD/BN, MTOT/BM), 256, SMEM_BYTES>>>();
    k_y<<<dim3(DD/BN, MTOT/BM), 256, SMEM_BYTES>>>();
    k_vtrans<<<dim3(DD/32, SS/32, BB), dim3(32, 8)>>>();
    k_scores<<<dim3(SS/BN, SS/BM, BB), 256, SMEM_BYTES>>>();
    k_softmax<<<dim3(SS, BB), 256>>>();
    k_pv<<<dim3(DD/BN, SS/BM, BB), 256, SMEM_BYTES>>>(out);
}

// round 12
// speedup vs baseline: 1.3857x; 1.0120x over previous
#include <cuda_runtime.h>
#include <cuda_fp16.h>
#include <cstdint>

#define BB 4
#define SS 4096
#define DD 1024
#define MTOT (BB*SS)

#define BM 128
#define BN 128
#define BK 32
#define TILE_B 8192                 // 128 rows x 64 bytes, swizzled
#define STAGE_B (2*TILE_B)          // A, B per stage = 16 KB
#define SMEM_BYTES  49152           // 3-stage -> 2 CTAs/SM
#define SMEM_BYTES6 98304           // 6-stage (k_M only)

// ---------------- device scratch ----------------
__device__ __half g_xh [(size_t)MTOT*DD];
__device__ __half g_Qh [(size_t)DD*DD];     // Q weight, fp16 row-major
__device__ __half g_Kh [(size_t)DD*DD];     // K weight, fp16 row-major
__device__ __half g_Wtv[(size_t)DD*DD];     // V^T: [n][k]
__device__ __half g_Mt [(size_t)DD*DD];     // (K Q^T): B-operand for y = x@M
__device__ __half g_Yh [(size_t)MTOT*DD];   // y = x @ (Q K^T)
__device__ __half g_Vxh[(size_t)MTOT*DD];   // Vx, fp16
__device__ __half g_Vth[(size_t)MTOT*DD];   // Vx^T: [b][d][s]
__device__ float  g_S  [(size_t)BB*SS*SS];
__device__ __half g_Ph [(size_t)BB*SS*SS];

// ---------------- asm helpers ----------------
__device__ __forceinline__ uint32_t smem_u32(const void* p){
    uint32_t a;
    asm("{ .reg .u64 t; cvta.to.shared.u64 t, %1; cvt.u32.u64 %0, t; }" : "=r"(a) : "l"(p));
    return a;
}
#define CPA(dst, src) asm volatile("cp.async.cg.shared.global [%0], [%1], 16;" :: "r"(dst), "l"(src))
#define CPC()  asm volatile("cp.async.commit_group;")

template<int N> __device__ __forceinline__ void cp_wait();
template<> __device__ __forceinline__ void cp_wait<0>(){ asm volatile("cp.async.wait_group 0;"); }
template<> __device__ __forceinline__ void cp_wait<1>(){ asm volatile("cp.async.wait_group 1;"); }
template<> __device__ __forceinline__ void cp_wait<2>(){ asm volatile("cp.async.wait_group 2;"); }
template<> __device__ __forceinline__ void cp_wait<3>(){ asm volatile("cp.async.wait_group 3;"); }
template<> __device__ __forceinline__ void cp_wait<4>(){ asm volatile("cp.async.wait_group 4;"); }

#define LDSM4(r0,r1,r2,r3,addr) \
    asm volatile("ldmatrix.sync.aligned.m8n8.x4.shared.b16 {%0,%1,%2,%3}, [%4];" \
        : "=r"(r0), "=r"(r1), "=r"(r2), "=r"(r3) : "r"(addr))

#define MMA(d, a, b) asm volatile( \
    "mma.sync.aligned.m16n8k16.row.col.f32.f16.f16.f32 " \
    "{%0,%1,%2,%3}, {%4,%5,%6,%7}, {%8,%9}, {%0,%1,%2,%3};" \
    : "+f"((d)[0]), "+f"((d)[1]), "+f"((d)[2]), "+f"((d)[3]) \
    : "r"((a)[0]), "r"((a)[1]), "r"((a)[2]), "r"((a)[3]), "r"((b)[0]), "r"((b)[1]))

// swizzled byte offset within a tile: row r (0..127), 16B chunk c (0..3)
__device__ __forceinline__ uint32_t swz(uint32_t r, uint32_t c){
    return r*64u + ((c ^ (r & 3u)) * 16u);
}

// ---------------- stage load (cp.async, swizzled): A, B ----------------
__device__ __forceinline__ void load_stage(uint32_t sm,
    const __half* A, size_t lda, int r0a,
    const __half* B, size_t ldb, int r0b,
    int k0, int tid)
{
#pragma unroll
    for (int i = 0; i < 2; i++){
        int id = tid + i*256;                 // 0..511
        uint32_t r = (uint32_t)(id >> 2), c = (uint32_t)(id & 3);
        uint32_t so = swz(r, c);
        size_t goa = (size_t)(r0a + (int)r)*lda + k0 + c*8;
        size_t gob = (size_t)(r0b + (int)r)*ldb + k0 + c*8;
        CPA(sm + so,          A + goa);
        CPA(sm + TILE_B + so, B + gob);
    }
}

// ---------------- stage compute: warp tile 32x64, 1-pass ----------------
__device__ __forceinline__ void compute_stage(uint32_t sm, int lane, int wm, int wn,
                                              float acc[2][8][4])
{
    const uint32_t aA = sm;
    const uint32_t aB = sm + TILE_B;
    const int ar = lane & 15;
    const int ac = lane >> 4;
    const int br = (lane & 7) | ((lane >> 4) << 3);
    const int bc = (lane >> 3) & 1;
#pragma unroll
    for (int ks = 0; ks < 2; ks++){
        uint32_t a[2][4], bh[8][2];
#pragma unroll
        for (int mi = 0; mi < 2; mi++){
            uint32_t r = (uint32_t)(wm*32 + mi*16 + ar);
            uint32_t off = swz(r, (uint32_t)(ks*2 + ac));
            LDSM4(a[mi][0], a[mi][1], a[mi][2], a[mi][3], aA + off);
        }
#pragma unroll
        for (int np = 0; np < 4; np++){
            uint32_t r = (uint32_t)(wn*64 + np*16 + br);
            uint32_t off = swz(r, (uint32_t)(ks*2 + bc));
            LDSM4(bh[2*np][0], bh[2*np][1], bh[2*np+1][0], bh[2*np+1][1], aB + off);
        }
#pragma unroll
        for (int mi = 0; mi < 2; mi++)
#pragma unroll
            for (int ni = 0; ni < 8; ni++)
                MMA(acc[mi][ni], a[mi], bh[ni]);
    }
}

// ---------------- GEMM mainloop (NST-stage pipeline, 1 sync/iter) ----------------
template<int NST>
__device__ __forceinline__ void gemm_run(uint32_t sm, int tid,
    const __half* A, size_t lda, int r0a,
    const __half* B, size_t ldb, int r0b,
    int ktiles, float acc[2][8][4])
{
    const int lane = tid & 31, wid = tid >> 5;
    const int wm = wid & 3, wn = wid >> 2;
    const int kend = ktiles * BK;

#pragma unroll
    for (int s = 0; s < NST - 1; s++){
        int k = min(s * BK, kend - BK);
        load_stage(sm + s*STAGE_B, A, lda, r0a, B, ldb, r0b, k, tid);
        CPC();
    }

    int buf = 0;
    int nxt = NST - 1;
    for (int kt = 0; kt < ktiles; kt++){
        cp_wait<NST-2>();
        __syncthreads();
        {
            int k = min((kt + NST - 1) * BK, kend - BK);
            load_stage(sm + nxt*STAGE_B, A, lda, r0a, B, ldb, r0b, k, tid);
            CPC();
        }
        compute_stage(sm + buf*STAGE_B, lane, wm, wn, acc);
        buf = (buf + 1 == NST) ? 0 : buf + 1;
        nxt = (nxt + 1 == NST) ? 0 : nxt + 1;
    }
}

// ---------------- kernel 1: x -> fp16 ----------------
__global__ void k_half_x(const float* __restrict__ x){
    size_t i = ((size_t)blockIdx.x * 256 + threadIdx.x) * 4;
    float4 v = *reinterpret_cast<const float4*>(x + i);
    __half2 h01{__float2half(v.x), __float2half(v.y)};
    __half2 h23{__float2half(v.z), __float2half(v.w)};
    *reinterpret_cast<__half2*>(g_xh + i)     = h01;
    *reinterpret_cast<__half2*>(g_xh + i + 2) = h23;
}

// ---------------- kernel 2a: Q,K weights -> fp16 row-major ----------------
__global__ void k_half_w(const float* __restrict__ Wq,
                         const float* __restrict__ Wk){
    const float* W = blockIdx.y ? Wk : Wq;
    __half* H      = blockIdx.y ? g_Kh : g_Qh;
    size_t i = ((size_t)blockIdx.x * 256 + threadIdx.x) * 4;
    float4 v = *reinterpret_cast<const float4*>(W + i);
    __half2 h01{__float2half(v.x), __float2half(v.y)};
    __half2 h23{__float2half(v.z), __float2half(v.w)};
    *reinterpret_cast<__half2*>(H + i)     = h01;
    *reinterpret_cast<__half2*>(H + i + 2) = h23;
}

// ---------------- kernel 2b: transpose V -> fp16 ----------------
__global__ void k_wtrans(const float* __restrict__ Wv){
    __shared__ float t[32][33];
    int tx = threadIdx.x, ty = threadIdx.y;
    int kb = blockIdx.y * 32, nb = blockIdx.x * 32;
#pragma unroll
    for (int j = 0; j < 4; j++)
        t[ty + j*8][tx] = Wv[(size_t)(kb + ty + j*8)*DD + nb + tx];
    __syncthreads();
#pragma unroll
    for (int j = 0; j < 4; j++){
        int n = nb + ty + j*8, k = kb + tx;
        g_Wtv[(size_t)n*DD + k] = __float2half(t[tx][ty + j*8]);
    }
}

// ---------------- kernel 3: Mt = K @ Q^T (deep pipeline; tiny grid) ----------
__global__ void __launch_bounds__(256, 1) k_M(){
    extern __shared__ __align__(128) char smem[];
    uint32_t sm = smem_u32(smem);
    const int tid = threadIdx.x;
    const int m0 = blockIdx.y*BM, n0 = blockIdx.x*BN;
    float acc[2][8][4] = {};
    gemm_run<6>(sm, tid, g_Kh, DD, m0, g_Qh, DD, n0, DD/BK, acc);
    const int lane = tid & 31, wid = tid >> 5, wm = wid & 3, wn = wid >> 2;
    const int r = lane >> 2, c = (lane & 3) * 2;
#pragma unroll
    for (int mi = 0; mi < 2; mi++)
#pragma unroll
        for (int ni = 0; ni < 8; ni++){
            int row = m0 + wm*32 + mi*16 + r;
            int col = n0 + wn*64 + ni*8 + c;
#pragma unroll
            for (int hrow = 0; hrow < 2; hrow++){
                __half2 hp{__float2half(acc[mi][ni][hrow*2+0]),
                           __float2half(acc[mi][ni][hrow*2+1])};
                *reinterpret_cast<__half2*>(g_Mt + (size_t)(row + hrow*8)*DD + col) = hp;
            }
        }
}

// ---------------- kernel 4: V projection -> fp16 ----------------
__global__ void __launch_bounds__(256, 2) k_proj_v(){
    extern __shared__ __align__(128) char smem[];
    uint32_t sm = smem_u32(smem);
    const int tid = threadIdx.x;
    const int m0 = blockIdx.y*BM, n0 = blockIdx.x*BN;
    float acc[2][8][4] = {};
    gemm_run<3>(sm, tid, g_xh, DD, m0, g_Wtv, DD, n0, DD/BK, acc);
    const int lane = tid & 31, wid = tid >> 5, wm = wid & 3, wn = wid >> 2;
    const int r = lane >> 2, c = (lane & 3) * 2;
#pragma unroll
    for (int mi = 0; mi < 2; mi++)
#pragma unroll
        for (int ni = 0; ni < 8; ni++){
            int row = m0 + wm*32 + mi*16 + r;
            int col = n0 + wn*64 + ni*8 + c;
#pragma unroll
            for (int hrow = 0; hrow < 2; hrow++){
                size_t o = (size_t)(row + hrow*8)*DD + col;
                __half2 hp{__float2half(acc[mi][ni][hrow*2+0]),
                           __float2half(acc[mi][ni][hrow*2+1])};
                *reinterpret_cast<__half2*>(g_Vxh + o) = hp;
            }
        }
}

// ---------------- kernel 5: y = x @ M (B = Mt) ----------------
__global__ void __launch_bounds__(256, 2) k_y(){
    extern __shared__ __align__(128) char smem[];
    uint32_t sm = smem_u32(smem);
    const int tid = threadIdx.x;
    const int m0 = blockIdx.y*BM, n0 = blockIdx.x*BN;
    float acc[2][8][4] = {};
    gemm_run<3>(sm, tid, g_xh, DD, m0, g_Mt, DD, n0, DD/BK, acc);
    const int lane = tid & 31, wid = tid >> 5, wm = wid & 3, wn = wid >> 2;
    const int r = lane >> 2, c = (lane & 3) * 2;
#pragma unroll
    for (int mi = 0; mi < 2; mi++)
#pragma unroll
        for (int ni = 0; ni < 8; ni++){
            int row = m0 + wm*32 + mi*16 + r;
            int col = n0 + wn*64 + ni*8 + c;
#pragma unroll
            for (int hrow = 0; hrow < 2; hrow++){
                __half2 hp{__float2half(acc[mi][ni][hrow*2+0]),
                           __float2half(acc[mi][ni][hrow*2+1])};
                *reinterpret_cast<__half2*>(g_Yh + (size_t)(row + hrow*8)*DD + col) = hp;
            }
        }
}

// ---------------- kernel 6: transpose Vx (fp16 in/out) ----------------
__global__ void k_vtrans(){
    const int b = blockIdx.z;
    const __half* Vx = g_Vxh + (size_t)b*SS*DD;
    __half* H = g_Vth + (size_t)b*DD*SS;
    __shared__ float t[32][33];
    int tx = threadIdx.x, ty = threadIdx.y;
    int s0 = blockIdx.y * 32, d0 = blockIdx.x * 32;
#pragma unroll
    for (int j = 0; j < 4; j++)
        t[ty + j*8][tx] = __half2float(Vx[(size_t)(s0 + ty + j*8)*DD + d0 + tx]);
    __syncthreads();
#pragma unroll
    for (int j = 0; j < 4; j++){
        int d = d0 + ty + j*8, s = s0 + tx;
        H[(size_t)d*SS + s] = __float2half(t[tx][ty + j*8]);
    }
}

// ---------------- kernel 7: scores = y @ x^T (lower-tri tiles) ----------------
__global__ void __launch_bounds__(256, 2) k_scores(){
    const int kt = blockIdx.x, qt = blockIdx.y, b = blockIdx.z;
    if (kt > qt) return;
    extern __shared__ __align__(128) char smem[];
    uint32_t sm = smem_u32(smem);
    const int tid = threadIdx.x;
    float acc[2][8][4] = {};
    gemm_run<3>(sm, tid,
                g_Yh + (size_t)b*SS*DD, DD, qt*BM,
                g_xh + (size_t)b*SS*DD, DD, kt*BN, DD/BK, acc);
    const int lane = tid & 31, wid = tid >> 5, wm = wid & 3, wn = wid >> 2;
    const int r = lane >> 2, c = (lane & 3) * 2;
    float* Sp = g_S + (size_t)b*SS*SS;
#pragma unroll
    for (int mi = 0; mi < 2; mi++)
#pragma unroll
        for (int ni = 0; ni < 8; ni++){
            int row = qt*BM + wm*32 + mi*16 + r;
            int col = kt*BN + wn*64 + ni*8 + c;
#pragma unroll
            for (int hrow = 0; hrow < 2; hrow++){
                size_t o = (size_t)(row + hrow*8)*SS + col;
                *reinterpret_cast<float2*>(Sp + o) =
                    make_float2(acc[mi][ni][hrow*2+0]*0.03125f,
                                acc[mi][ni][hrow*2+1]*0.03125f);
            }
        }
}

// ---------------- kernel 8: softmax -> fp16 probs + pad ----------------
__global__ void k_softmax(){
    const int q = blockIdx.x;
    const int b = blockIdx.y;
    const float* row = g_S + (size_t)b*SS*SS + (size_t)q*SS;
    __half* Ph = g_Ph + (size_t)b*SS*SS + (size_t)q*SS;
    const int len = q + 1;

    __shared__ float buf[SS];
    __shared__ float red[256];
    const int tid = threadIdx.x;

    float mx = -1e30f;
    for (int i = tid; i < len; i += 256){
        float v = row[i];
        buf[i] = v;
        mx = fmaxf(mx, v);
    }
    red[tid] = mx;
    __syncthreads();
    for (int s = 128; s > 0; s >>= 1){
        if (tid < s) red[tid] = fmaxf(red[tid], red[tid + s]);
        __syncthreads();
    }
    mx = red[0];
    __syncthreads();

    float sum = 0.f;
    for (int i = tid; i < len; i += 256){
        float e = __expf(buf[i] - mx);
        buf[i] = e;
        sum += e;
    }
    red[tid] = sum;
    __syncthreads();
    for (int s = 128; s > 0; s >>= 1){
        if (tid < s) red[tid] += red[tid + s];
        __syncthreads();
    }
    const float inv = 1.0f / red[0];
    __syncthreads();

    for (int i = tid; i < len; i += 256)
        Ph[i] = __float2half(buf[i] * inv);
    // zero-pad to the 128-tile boundary so PV's diagonal tiles read zeros
    const int bound = ((q >> 7) + 1) << 7;
    const __half z = __float2half(0.f);
    for (int i = len + tid; i < bound; i += 256) Ph[i] = z;
}

// ---------------- kernel 9: O = P @ V (triangular K range) ----------------
__global__ void __launch_bounds__(256, 2) k_pv(float* __restrict__ Out){
    const int dt = blockIdx.x, qt = blockIdx.y, b = blockIdx.z;
    extern __shared__ __align__(128) char smem[];
    uint32_t sm = smem_u32(smem);
    const int tid = threadIdx.x;
    float acc[2][8][4] = {};
    const int ktiles = (qt + 1) * (BM / BK);   // keys up to (qt+1)*128
    gemm_run<3>(sm, tid,
                g_Ph  + (size_t)b*SS*SS, SS, qt*BM,
                g_Vth + (size_t)b*DD*SS, SS, dt*BN, ktiles, acc);
    const int lane = tid & 31, wid = tid >> 5, wm = wid & 3, wn = wid >> 2;
    const int r = lane >> 2, c = (lane & 3) * 2;
#pragma unroll
    for (int mi = 0; mi < 2; mi++)
#pragma unroll
        for (int ni = 0; ni < 8; ni++){
            int row = qt*BM + wm*32 + mi*16 + r;
            int col = dt*BN + wn*64 + ni*8 + c;
#pragma unroll
            for (int hrow = 0; hrow < 2; hrow++){
                size_t o = ((size_t)b*SS + row + hrow*8)*DD + col;
                *reinterpret_cast<float2*>(Out + o) =
                    make_float2(acc[mi][ni][hrow*2+0], acc[mi][ni][hrow*2+1]);
            }
        }
}

// ---------------- host ----------------
extern "C" void kernel_launch(void* const* d_in, const int* in_sizes, int n_in,
                              void* d_out, int out_size) {
    const float* x  = (const float*)d_in[0];
    const float* Q  = (const float*)d_in[1];
    const float* K  = (const float*)d_in[2];
    const float* V  = (const float*)d_in[3];
    float* out = (float*)d_out;

    cudaFuncSetAttribute(k_M,      cudaFuncAttributeMaxDynamicSharedMemorySize, SMEM_BYTES6);
    cudaFuncSetAttribute(k_proj_v, cudaFuncAttributeMaxDynamicSharedMemorySize, SMEM_BYTES);
    cudaFuncSetAttribute(k_y,      cudaFuncAttributeMaxDynamicSharedMemorySize, SMEM_BYTES);
    cudaFuncSetAttribute(k_scores, cudaFuncAttributeMaxDynamicSharedMemorySize, SMEM_BYTES);
    cudaFuncSetAttribute(k_pv,     cudaFuncAttributeMaxDynamicSharedMemorySize, SMEM_BYTES);

    k_half_x<<<(unsigned)((size_t)MTOT*DD/1024), 256>>>(x);
    k_half_w<<<dim3(DD*DD/1024, 2), 256>>>(Q, K);
    k_wtrans<<<dim3(DD/32, DD/32), dim3(32, 8)>>>(V);
    k_M<<<dim3(DD/BN, DD/BM), 256, SMEM_BYTES6>>>();
    k_proj_v<<<dim3(DD/BN, MTOT/BM), 256, SMEM_BYTES>>>();
    k_y<<<dim3(DD/BN, MTOT/BM), 256, SMEM_BYTES>>>();
    k_vtrans<<<dim3(DD/32, SS/32, BB), dim3(32, 8)>>>();
    k_scores<<<dim3(SS/BN, SS/BM, BB), 256, SMEM_BYTES>>>();
    k_softmax<<<dim3(SS, BB), 256>>>();
    k_pv<<<dim3(DD/BN, SS/BM, BB), 256, SMEM_BYTES>>>(out);
}

// round 13
// speedup vs baseline: 1.7271x; 1.2464x over previous
#include <cuda_runtime.h>
#include <cuda_fp16.h>
#include <cstdint>

#define BB 4
#define SS 4096
#define DD 1024
#define MTOT (BB*SS)

#define BM 128
#define BN 128
#define BK 32
#define TILE_B 8192                 // 128 rows x 64 bytes, swizzled
#define STAGE_B (2*TILE_B)          // A, B per stage = 16 KB
#define SMEM_BYTES  49152           // 3-stage -> 2 CTAs/SM (128 thr each)
#define SMEM_BYTES6 98304           // 6-stage (k_M only)
#define NTHR 128                    // 4 warps: 2x2 of 64x64 warp tiles

// ---------------- device scratch ----------------
__device__ __half g_xh [(size_t)MTOT*DD];
__device__ __half g_Qh [(size_t)DD*DD];
__device__ __half g_Kh [(size_t)DD*DD];
__device__ __half g_Wtv[(size_t)DD*DD];     // V^T: [n][k]
__device__ __half g_Mt [(size_t)DD*DD];     // (K Q^T)
__device__ __half g_Yh [(size_t)MTOT*DD];   // y = x @ (Q K^T)
__device__ __half g_Vxh[(size_t)MTOT*DD];
__device__ __half g_Vth[(size_t)MTOT*DD];   // Vx^T: [b][d][s]
__device__ float  g_S  [(size_t)BB*SS*SS];
__device__ __half g_Ph [(size_t)BB*SS*SS];

// ---------------- asm helpers ----------------
__device__ __forceinline__ uint32_t smem_u32(const void* p){
    uint32_t a;
    asm("{ .reg .u64 t; cvta.to.shared.u64 t, %1; cvt.u32.u64 %0, t; }" : "=r"(a) : "l"(p));
    return a;
}
#define CPA(dst, src) asm volatile("cp.async.cg.shared.global [%0], [%1], 16;" :: "r"(dst), "l"(src))
#define CPC()  asm volatile("cp.async.commit_group;")

template<int N> __device__ __forceinline__ void cp_wait();
template<> __device__ __forceinline__ void cp_wait<1>(){ asm volatile("cp.async.wait_group 1;"); }
template<> __device__ __forceinline__ void cp_wait<4>(){ asm volatile("cp.async.wait_group 4;"); }

#define LDSM4(r0,r1,r2,r3,addr) \
    asm volatile("ldmatrix.sync.aligned.m8n8.x4.shared.b16 {%0,%1,%2,%3}, [%4];" \
        : "=r"(r0), "=r"(r1), "=r"(r2), "=r"(r3) : "r"(addr))

#define MMA(d, a, b) asm volatile( \
    "mma.sync.aligned.m16n8k16.row.col.f32.f16.f16.f32 " \
    "{%0,%1,%2,%3}, {%4,%5,%6,%7}, {%8,%9}, {%0,%1,%2,%3};" \
    : "+f"((d)[0]), "+f"((d)[1]), "+f"((d)[2]), "+f"((d)[3]) \
    : "r"((a)[0]), "r"((a)[1]), "r"((a)[2]), "r"((a)[3]), "r"((b)[0]), "r"((b)[1]))

// swizzled byte offset within a tile: row r (0..127), 16B chunk c (0..3)
__device__ __forceinline__ uint32_t swz(uint32_t r, uint32_t c){
    return r*64u + ((c ^ (r & 3u)) * 16u);
}

// ---------------- stage load (cp.async, swizzled): A, B — 128 threads -------
__device__ __forceinline__ void load_stage(uint32_t sm,
    const __half* A, size_t lda, int r0a,
    const __half* B, size_t ldb, int r0b,
    int k0, int tid)
{
#pragma unroll
    for (int i = 0; i < 4; i++){
        int id = tid + i*NTHR;                // 0..511
        uint32_t r = (uint32_t)(id >> 2), c = (uint32_t)(id & 3);
        uint32_t so = swz(r, c);
        size_t goa = (size_t)(r0a + (int)r)*lda + k0 + c*8;
        size_t gob = (size_t)(r0b + (int)r)*ldb + k0 + c*8;
        CPA(sm + so,          A + goa);
        CPA(sm + TILE_B + so, B + gob);
    }
}

// ---------------- stage compute: warp tile 64x64, 1-pass ----------------
__device__ __forceinline__ void compute_stage(uint32_t sm, int lane, int wm, int wn,
                                              float acc[4][8][4])
{
    const uint32_t aA = sm;
    const uint32_t aB = sm + TILE_B;
    const int ar = lane & 15;
    const int ac = lane >> 4;
    const int br = (lane & 7) | ((lane >> 4) << 3);
    const int bc = (lane >> 3) & 1;
#pragma unroll
    for (int ks = 0; ks < 2; ks++){
        uint32_t a[4][4], bh[8][2];
#pragma unroll
        for (int mi = 0; mi < 4; mi++){
            uint32_t r = (uint32_t)(wm*64 + mi*16 + ar);
            uint32_t off = swz(r, (uint32_t)(ks*2 + ac));
            LDSM4(a[mi][0], a[mi][1], a[mi][2], a[mi][3], aA + off);
        }
#pragma unroll
        for (int np = 0; np < 4; np++){
            uint32_t r = (uint32_t)(wn*64 + np*16 + br);
            uint32_t off = swz(r, (uint32_t)(ks*2 + bc));
            LDSM4(bh[2*np][0], bh[2*np][1], bh[2*np+1][0], bh[2*np+1][1], aB + off);
        }
#pragma unroll
        for (int mi = 0; mi < 4; mi++)
#pragma unroll
            for (int ni = 0; ni < 8; ni++)
                MMA(acc[mi][ni], a[mi], bh[ni]);
    }
}

// ---------------- GEMM mainloop (NST-stage pipeline, 1 sync/iter) ----------------
template<int NST>
__device__ __forceinline__ void gemm_run(uint32_t sm, int tid,
    const __half* A, size_t lda, int r0a,
    const __half* B, size_t ldb, int r0b,
    int ktiles, float acc[4][8][4])
{
    const int lane = tid & 31, wid = tid >> 5;
    const int wm = wid & 1, wn = wid >> 1;
    const int kend = ktiles * BK;

#pragma unroll
    for (int s = 0; s < NST - 1; s++){
        int k = min(s * BK, kend - BK);
        load_stage(sm + s*STAGE_B, A, lda, r0a, B, ldb, r0b, k, tid);
        CPC();
    }

    int buf = 0;
    int nxt = NST - 1;
    for (int kt = 0; kt < ktiles; kt++){
        cp_wait<NST-2>();
        __syncthreads();
        {
            int k = min((kt + NST - 1) * BK, kend - BK);
            load_stage(sm + nxt*STAGE_B, A, lda, r0a, B, ldb, r0b, k, tid);
            CPC();
        }
        compute_stage(sm + buf*STAGE_B, lane, wm, wn, acc);
        buf = (buf + 1 == NST) ? 0 : buf + 1;
        nxt = (nxt + 1 == NST) ? 0 : nxt + 1;
    }
}

// Epilogue index helper (warp 64x64): row/col of acc[mi][ni] quad
// row = base_m + wm*64 + mi*16 + (lane>>2) + hrow*8 ; col = base_n + wn*64 + ni*8 + (lane&3)*2

// ---------------- kernel 1: x -> fp16 ----------------
__global__ void k_half_x(const float* __restrict__ x){
    size_t i = ((size_t)blockIdx.x * 256 + threadIdx.x) * 4;
    float4 v = *reinterpret_cast<const float4*>(x + i);
    __half2 h01{__float2half(v.x), __float2half(v.y)};
    __half2 h23{__float2half(v.z), __float2half(v.w)};
    *reinterpret_cast<__half2*>(g_xh + i)     = h01;
    *reinterpret_cast<__half2*>(g_xh + i + 2) = h23;
}

// ---------------- kernel 2a: Q,K weights -> fp16 row-major ----------------
__global__ void k_half_w(const float* __restrict__ Wq,
                         const float* __restrict__ Wk){
    const float* W = blockIdx.y ? Wk : Wq;
    __half* H      = blockIdx.y ? g_Kh : g_Qh;
    size_t i = ((size_t)blockIdx.x * 256 + threadIdx.x) * 4;
    float4 v = *reinterpret_cast<const float4*>(W + i);
    __half2 h01{__float2half(v.x), __float2half(v.y)};
    __half2 h23{__float2half(v.z), __float2half(v.w)};
    *reinterpret_cast<__half2*>(H + i)     = h01;
    *reinterpret_cast<__half2*>(H + i + 2) = h23;
}

// ---------------- kernel 2b: transpose V -> fp16 ----------------
__global__ void k_wtrans(const float* __restrict__ Wv){
    __shared__ float t[32][33];
    int tx = threadIdx.x, ty = threadIdx.y;
    int kb = blockIdx.y * 32, nb = blockIdx.x * 32;
#pragma unroll
    for (int j = 0; j < 4; j++)
        t[ty + j*8][tx] = Wv[(size_t)(kb + ty + j*8)*DD + nb + tx];
    __syncthreads();
#pragma unroll
    for (int j = 0; j < 4; j++){
        int n = nb + ty + j*8, k = kb + tx;
        g_Wtv[(size_t)n*DD + k] = __float2half(t[tx][ty + j*8]);
    }
}

// ---------------- kernel 3: Mt = K @ Q^T ----------------
__global__ void __launch_bounds__(NTHR, 1) k_M(){
    extern __shared__ __align__(128) char smem[];
    uint32_t sm = smem_u32(smem);
    const int tid = threadIdx.x;
    const int m0 = blockIdx.y*BM, n0 = blockIdx.x*BN;
    float acc[4][8][4] = {};
    gemm_run<6>(sm, tid, g_Kh, DD, m0, g_Qh, DD, n0, DD/BK, acc);
    const int lane = tid & 31, wid = tid >> 5, wm = wid & 1, wn = wid >> 1;
    const int r = lane >> 2, c = (lane & 3) * 2;
#pragma unroll
    for (int mi = 0; mi < 4; mi++)
#pragma unroll
        for (int ni = 0; ni < 8; ni++){
            int row = m0 + wm*64 + mi*16 + r;
            int col = n0 + wn*64 + ni*8 + c;
#pragma unroll
            for (int hrow = 0; hrow < 2; hrow++){
                __half2 hp{__float2half(acc[mi][ni][hrow*2+0]),
                           __float2half(acc[mi][ni][hrow*2+1])};
                *reinterpret_cast<__half2*>(g_Mt + (size_t)(row + hrow*8)*DD + col) = hp;
            }
        }
}

// ---------------- kernel 4: V projection -> fp16 ----------------
__global__ void __launch_bounds__(NTHR, 2) k_proj_v(){
    extern __shared__ __align__(128) char smem[];
    uint32_t sm = smem_u32(smem);
    const int tid = threadIdx.x;
    const int m0 = blockIdx.y*BM, n0 = blockIdx.x*BN;
    float acc[4][8][4] = {};
    gemm_run<3>(sm, tid, g_xh, DD, m0, g_Wtv, DD, n0, DD/BK, acc);
    const int lane = tid & 31, wid = tid >> 5, wm = wid & 1, wn = wid >> 1;
    const int r = lane >> 2, c = (lane & 3) * 2;
#pragma unroll
    for (int mi = 0; mi < 4; mi++)
#pragma unroll
        for (int ni = 0; ni < 8; ni++){
            int row = m0 + wm*64 + mi*16 + r;
            int col = n0 + wn*64 + ni*8 + c;
#pragma unroll
            for (int hrow = 0; hrow < 2; hrow++){
                size_t o = (size_t)(row + hrow*8)*DD + col;
                __half2 hp{__float2half(acc[mi][ni][hrow*2+0]),
                           __float2half(acc[mi][ni][hrow*2+1])};
                *reinterpret_cast<__half2*>(g_Vxh + o) = hp;
            }
        }
}

// ---------------- kernel 5: y = x @ M ----------------
__global__ void __launch_bounds__(NTHR, 2) k_y(){
    extern __shared__ __align__(128) char smem[];
    uint32_t sm = smem_u32(smem);
    const int tid = threadIdx.x;
    const int m0 = blockIdx.y*BM, n0 = blockIdx.x*BN;
    float acc[4][8][4] = {};
    gemm_run<3>(sm, tid, g_xh, DD, m0, g_Mt, DD, n0, DD/BK, acc);
    const int lane = tid & 31, wid = tid >> 5, wm = wid & 1, wn = wid >> 1;
    const int r = lane >> 2, c = (lane & 3) * 2;
#pragma unroll
    for (int mi = 0; mi < 4; mi++)
#pragma unroll
        for (int ni = 0; ni < 8; ni++){
            int row = m0 + wm*64 + mi*16 + r;
            int col = n0 + wn*64 + ni*8 + c;
#pragma unroll
            for (int hrow = 0; hrow < 2; hrow++){
                __half2 hp{__float2half(acc[mi][ni][hrow*2+0]),
                           __float2half(acc[mi][ni][hrow*2+1])};
                *reinterpret_cast<__half2*>(g_Yh + (size_t)(row + hrow*8)*DD + col) = hp;
            }
        }
}

// ---------------- kernel 6: transpose Vx (fp16 in/out) ----------------
__global__ void k_vtrans(){
    const int b = blockIdx.z;
    const __half* Vx = g_Vxh + (size_t)b*SS*DD;
    __half* H = g_Vth + (size_t)b*DD*SS;
    __shared__ float t[32][33];
    int tx = threadIdx.x, ty = threadIdx.y;
    int s0 = blockIdx.y * 32, d0 = blockIdx.x * 32;
#pragma unroll
    for (int j = 0; j < 4; j++)
        t[ty + j*8][tx] = __half2float(Vx[(size_t)(s0 + ty + j*8)*DD + d0 + tx]);
    __syncthreads();
#pragma unroll
    for (int j = 0; j < 4; j++){
        int d = d0 + ty + j*8, s = s0 + tx;
        H[(size_t)d*SS + s] = __float2half(t[tx][ty + j*8]);
    }
}

// ---------------- kernel 7: scores = y @ x^T (lower-tri tiles) ----------------
__global__ void __launch_bounds__(NTHR, 2) k_scores(){
    const int kt = blockIdx.x, qt = blockIdx.y, b = blockIdx.z;
    if (kt > qt) return;
    extern __shared__ __align__(128) char smem[];
    uint32_t sm = smem_u32(smem);
    const int tid = threadIdx.x;
    float acc[4][8][4] = {};
    gemm_run<3>(sm, tid,
                g_Yh + (size_t)b*SS*DD, DD, qt*BM,
                g_xh + (size_t)b*SS*DD, DD, kt*BN, DD/BK, acc);
    const int lane = tid & 31, wid = tid >> 5, wm = wid & 1, wn = wid >> 1;
    const int r = lane >> 2, c = (lane & 3) * 2;
    float* Sp = g_S + (size_t)b*SS*SS;
#pragma unroll
    for (int mi = 0; mi < 4; mi++)
#pragma unroll
        for (int ni = 0; ni < 8; ni++){
            int row = qt*BM + wm*64 + mi*16 + r;
            int col = kt*BN + wn*64 + ni*8 + c;
#pragma unroll
            for (int hrow = 0; hrow < 2; hrow++){
                size_t o = (size_t)(row + hrow*8)*SS + col;
                *reinterpret_cast<float2*>(Sp + o) =
                    make_float2(acc[mi][ni][hrow*2+0]*0.03125f,
                                acc[mi][ni][hrow*2+1]*0.03125f);
            }
        }
}

// ---------------- kernel 8: softmax -> fp16 probs + pad ----------------
__global__ void k_softmax(){
    const int q = blockIdx.x;
    const int b = blockIdx.y;
    const float* row = g_S + (size_t)b*SS*SS + (size_t)q*SS;
    __half* Ph = g_Ph + (size_t)b*SS*SS + (size_t)q*SS;
    const int len = q + 1;

    __shared__ float buf[SS];
    __shared__ float red[256];
    const int tid = threadIdx.x;

    float mx = -1e30f;
    for (int i = tid; i < len; i += 256){
        float v = row[i];
        buf[i] = v;
        mx = fmaxf(mx, v);
    }
    red[tid] = mx;
    __syncthreads();
    for (int s = 128; s > 0; s >>= 1){
        if (tid < s) red[tid] = fmaxf(red[tid], red[tid + s]);
        __syncthreads();
    }
    mx = red[0];
    __syncthreads();

    float sum = 0.f;
    for (int i = tid; i < len; i += 256){
        float e = __expf(buf[i] - mx);
        buf[i] = e;
        sum += e;
    }
    red[tid] = sum;
    __syncthreads();
    for (int s = 128; s > 0; s >>= 1){
        if (tid < s) red[tid] += red[tid + s];
        __syncthreads();
    }
    const float inv = 1.0f / red[0];
    __syncthreads();

    for (int i = tid; i < len; i += 256)
        Ph[i] = __float2half(buf[i] * inv);
    const int bound = ((q >> 7) + 1) << 7;
    const __half z = __float2half(0.f);
    for (int i = len + tid; i < bound; i += 256) Ph[i] = z;
}

// ---------------- kernel 9: O = P @ V (triangular; longest-first) ----------
__global__ void __launch_bounds__(NTHR, 2) k_pv(float* __restrict__ Out){
    const int dt = blockIdx.x, b = blockIdx.z;
    const int qt = (int)gridDim.y - 1 - (int)blockIdx.y;   // longest first
    extern __shared__ __align__(128) char smem[];
    uint32_t sm = smem_u32(smem);
    const int tid = threadIdx.x;
    float acc[4][8][4] = {};
    const int ktiles = (qt + 1) * (BM / BK);
    gemm_run<3>(sm, tid,
                g_Ph  + (size_t)b*SS*SS, SS, qt*BM,
                g_Vth + (size_t)b*DD*SS, SS, dt*BN, ktiles, acc);
    const int lane = tid & 31, wid = tid >> 5, wm = wid & 1, wn = wid >> 1;
    const int r = lane >> 2, c = (lane & 3) * 2;
#pragma unroll
    for (int mi = 0; mi < 4; mi++)
#pragma unroll
        for (int ni = 0; ni < 8; ni++){
            int row = qt*BM + wm*64 + mi*16 + r;
            int col = dt*BN + wn*64 + ni*8 + c;
#pragma unroll
            for (int hrow = 0; hrow < 2; hrow++){
                size_t o = ((size_t)b*SS + row + hrow*8)*DD + col;
                *reinterpret_cast<float2*>(Out + o) =
                    make_float2(acc[mi][ni][hrow*2+0], acc[mi][ni][hrow*2+1]);
            }
        }
}

// ---------------- host ----------------
extern "C" void kernel_launch(void* const* d_in, const int* in_sizes, int n_in,
                              void* d_out, int out_size) {
    const float* x  = (const float*)d_in[0];
    const float* Q  = (const float*)d_in[1];
    const float* K  = (const float*)d_in[2];
    const float* V  = (const float*)d_in[3];
    float* out = (float*)d_out;

    cudaFuncSetAttribute(k_M,      cudaFuncAttributeMaxDynamicSharedMemorySize, SMEM_BYTES6);
    cudaFuncSetAttribute(k_proj_v, cudaFuncAttributeMaxDynamicSharedMemorySize, SMEM_BYTES);
    cudaFuncSetAttribute(k_y,      cudaFuncAttributeMaxDynamicSharedMemorySize, SMEM_BYTES);
    cudaFuncSetAttribute(k_scores, cudaFuncAttributeMaxDynamicSharedMemorySize, SMEM_BYTES);
    cudaFuncSetAttribute(k_pv,     cudaFuncAttributeMaxDynamicSharedMemorySize, SMEM_BYTES);

    k_half_x<<<(unsigned)((size_t)MTOT*DD/1024), 256>>>(x);
    k_half_w<<<dim3(DD*DD/1024, 2), 256>>>(Q, K);
    k_wtrans<<<dim3(DD/32, DD/32), dim3(32, 8)>>>(V);
    k_M<<<dim3(DD/BN, DD/BM), NTHR, SMEM_BYTES6>>>();
    k_proj_v<<<dim3(DD/BN, MTOT/BM), NTHR, SMEM_BYTES>>>();
    k_y<<<dim3(DD/BN, MTOT/BM), NTHR, SMEM_BYTES>>>();
    k_vtrans<<<dim3(DD/32, SS/32, BB), dim3(32, 8)>>>();
    k_scores<<<dim3(SS/BN, SS/BM, BB), NTHR, SMEM_BYTES>>>();
    k_softmax<<<dim3(SS, BB), 256>>>();
    k_pv<<<dim3(DD/BN, SS/BM, BB), NTHR, SMEM_BYTES>>>(out);
}